// round 3
// baseline (speedup 1.0000x reference)
#include <cuda_runtime.h>
#include <stdint.h>

#define THRESH   0.05f
#define SPEC     0.95f      // speculative collection cutoff (fast path)
#define NBINS    4096
#define CAP      65536
#define RANKMAX  4096
#define SH_N     1024

__device__ unsigned int g_bar;      // monotonic grid-barrier counter (never reset)
__device__ unsigned int g_count;    // fast-path candidates   (reset at end of run)
__device__ unsigned int g_count2;   // fallback candidates    (reset at end of run)
__device__ unsigned int g_hist[NBINS];
__device__ unsigned int g_cand_val[CAP];
__device__ unsigned int g_cand_idx[CAP];
__device__ unsigned int g_cand2_val[CAP];
__device__ unsigned int g_cand2_idx[CAP];

// Software grid barrier. Safe across graph replays: counter is monotonic,
// each arrival waits for the next multiple of nblocks above its ticket.
// Requires all blocks co-resident (grid sized via occupancy API on host).
__device__ __forceinline__ void grid_barrier(unsigned int nblocks) {
    __syncthreads();
    __threadfence();
    if (threadIdx.x == 0) {
        unsigned int old = atomicAdd(&g_bar, 1u);
        unsigned int target = (old / nblocks + 1u) * nblocks;
        while (atomicAdd(&g_bar, 0u) < target) __nanosleep(128);
    }
    __syncthreads();
}

__device__ __forceinline__ void spec_push(float v, unsigned int e) {
    if (v > SPEC) {
        unsigned int pos = atomicAdd(&g_count, 1u);
        if (pos < CAP) {
            g_cand_val[pos] = __float_as_uint(v);
            g_cand_idx[pos] = e;
        }
    }
}

// Process one float4 (4 score elements starting at flat index e).
// box_scores computed inline: ps[r]*os[r] are L1-broadcast hits.
__device__ __forceinline__ void proc4(const float4& h, unsigned int e,
                                      unsigned int K, unsigned long long magic,
                                      const float* __restrict__ ps,
                                      const float* __restrict__ os) {
    unsigned int r = (unsigned int)(((unsigned long long)e * magic) >> 33);
    unsigned int c = e - r * K;
    float bs0 = ps[r] * os[r];
    float v0, v1, v2, v3;
    if (c + 3 < K) {
        v0 = h.x * bs0; v1 = h.y * bs0; v2 = h.z * bs0; v3 = h.w * bs0;
    } else {
        // full groups that cross a row boundary always have row r+1 in range
        float bs1 = ps[r + 1] * os[r + 1];
        v0 = h.x * bs0;
        v1 = h.y * ((c + 1 < K) ? bs0 : bs1);
        v2 = h.z * ((c + 2 < K) ? bs0 : bs1);
        v3 = h.w * ((c + 3 < K) ? bs0 : bs1);
    }
    spec_push(v0, e); spec_push(v1, e + 1); spec_push(v2, e + 2); spec_push(v3, e + 3);
}

// Exact rank (value desc, index asc — matches jax.lax.top_k tie-breaking) of n
// candidates, then gather into the flat output. Runs in block 0 only.
//   [0,T) scores | [T,5T) pboxes | [5T,9T) oboxes | [9T,10T) ocls
//   [10T,11T) action | [11T,12T) valid
__device__ void rank_and_write(const unsigned int* __restrict__ cval,
                               const unsigned int* __restrict__ cidx,
                               unsigned int n,
                               const float4* __restrict__ pb,
                               const float4* __restrict__ ob,
                               const int* __restrict__ ocls,
                               float* __restrict__ out,
                               unsigned int K, int T, unsigned long long magic) {
    __shared__ unsigned int sval[SH_N];
    __shared__ unsigned int sidx[SH_N];
    const unsigned int* vals = cval;
    const unsigned int* idxs = cidx;
    if (n <= SH_N) {
        for (unsigned int i = threadIdx.x; i < n; i += blockDim.x) {
            sval[i] = cval[i];
            sidx[i] = cidx[i];
        }
        __syncthreads();
        vals = sval; idxs = sidx;
    }
    for (unsigned int i = threadIdx.x; i < n; i += blockDim.x) {
        unsigned int vb = vals[i];
        unsigned int ix = idxs[i];
        unsigned int rank = 0;
        for (unsigned int j = 0; j < n; j++) {
            unsigned int vj = vals[j];
            // positive floats: uint compare == float compare
            rank += (vj > vb) || (vj == vb && idxs[j] < ix);
        }
        if (rank < (unsigned int)T) {
            unsigned int pair = (unsigned int)(((unsigned long long)ix * magic) >> 33);
            unsigned int act  = ix - pair * K;
            out[rank] = __uint_as_float(vb);
            float4 p = pb[pair];
            float4 o = ob[pair];
            out[T + 4 * rank + 0] = p.x;
            out[T + 4 * rank + 1] = p.y;
            out[T + 4 * rank + 2] = p.z;
            out[T + 4 * rank + 3] = p.w;
            out[5 * T + 4 * rank + 0] = o.x;
            out[5 * T + 4 * rank + 1] = o.y;
            out[5 * T + 4 * rank + 2] = o.z;
            out[5 * T + 4 * rank + 3] = o.w;
            out[9 * T + rank]  = (float)ocls[pair];
            out[10 * T + rank] = (float)act;
            out[11 * T + rank] = 1.0f;
        }
    }
    // pad unfilled slots (n < T never occurs for this data distribution)
    for (int s = threadIdx.x; s < T; s += blockDim.x) {
        if ((unsigned int)s >= n) {
            out[s] = 0.0f;
            #pragma unroll
            for (int d = 0; d < 4; d++) {
                out[T + 4 * s + d]     = 0.0f;
                out[5 * T + 4 * s + d] = 0.0f;
            }
            out[9 * T + s]  = 0.0f;
            out[10 * T + s] = 0.0f;
            out[11 * T + s] = 0.0f;
        }
    }
}

// ---------------------------------------------------------------------------
// ONE fused persistent kernel: stream + speculative collect -> barrier ->
// (fast: rank+gather) / (fallback: hist -> cutoff -> collect -> rank+gather).
// ---------------------------------------------------------------------------
__global__ void __launch_bounds__(256)
k_fused(const float4* __restrict__ hoi4,
        const float*  __restrict__ ps,
        const float*  __restrict__ os,
        const float4* __restrict__ pb,
        const float4* __restrict__ ob,
        const int*    __restrict__ ocls,
        float*        __restrict__ out,
        unsigned int nvec, unsigned int N, unsigned int K,
        unsigned long long magic, int T, unsigned int nblocks) {
    // ---- Phase 1: speculative streaming pass ----
    {
        unsigned int stride = gridDim.x * blockDim.x;
        unsigned int q = blockIdx.x * blockDim.x + threadIdx.x;
        for (; q + 3u * stride < nvec; q += 4u * stride) {
            float4 h0 = hoi4[q];
            float4 h1 = hoi4[q + stride];
            float4 h2 = hoi4[q + 2u * stride];
            float4 h3 = hoi4[q + 3u * stride];
            proc4(h0, q * 4u, K, magic, ps, os);
            proc4(h1, (q + stride) * 4u, K, magic, ps, os);
            proc4(h2, (q + 2u * stride) * 4u, K, magic, ps, os);
            proc4(h3, (q + 3u * stride) * 4u, K, magic, ps, os);
        }
        for (; q < nvec; q += stride) {
            float4 h = hoi4[q];
            proc4(h, q * 4u, K, magic, ps, os);
        }
        if (blockIdx.x == 0 && threadIdx.x == 0) {
            for (unsigned int e = nvec * 4u; e < N; e++) {
                unsigned int r = (unsigned int)(((unsigned long long)e * magic) >> 33);
                float v = ((const float*)hoi4)[e] * ps[r] * os[r];
                spec_push(v, e);
            }
        }
    }

    grid_barrier(nblocks);

    unsigned int n = atomicAdd(&g_count, 0u);  // same value in every block
    bool fast = (n >= (unsigned int)T && n <= RANKMAX);

    if (fast) {
        if (blockIdx.x == 0) {
            rank_and_write(g_cand_val, g_cand_idx, n, pb, ob, ocls, out, K, T, magic);
            if (threadIdx.x == 0) { g_count = 0; g_count2 = 0; }
        }
        return;
    }

    // ================= Fallback (exact, never taken for bench data) ==========
    // zero histogram
    {
        unsigned int stride = gridDim.x * blockDim.x;
        for (unsigned int i = blockIdx.x * blockDim.x + threadIdx.x; i < NBINS; i += stride)
            g_hist[i] = 0;
    }
    grid_barrier(nblocks);

    // histogram of v > THRESH into 4096 linear bins (shared-privatized)
    {
        __shared__ unsigned int sh[NBINS];
        for (int i = threadIdx.x; i < NBINS; i += blockDim.x) sh[i] = 0;
        __syncthreads();
        unsigned int stride = gridDim.x * blockDim.x;
        for (unsigned int q = blockIdx.x * blockDim.x + threadIdx.x; q < nvec; q += stride) {
            float4 h = hoi4[q];
            unsigned int e = q * 4u;
            unsigned int r = (unsigned int)(((unsigned long long)e * magic) >> 33);
            unsigned int c = e - r * K;
            float bs0 = ps[r] * os[r];
            float bs1 = (c + 3 >= K) ? ps[r + 1] * os[r + 1] : bs0;
            float hv[4] = {h.x, h.y, h.z, h.w};
            #pragma unroll
            for (int j = 0; j < 4; j++) {
                float v = hv[j] * ((c + (unsigned)j < K) ? bs0 : bs1);
                if (v > THRESH) {
                    unsigned int b = (unsigned int)(v * (float)NBINS);
                    if (b > NBINS - 1) b = NBINS - 1;
                    atomicAdd(&sh[b], 1u);
                }
            }
        }
        if (blockIdx.x == 0 && threadIdx.x == 0) {
            for (unsigned int e = nvec * 4u; e < N; e++) {
                unsigned int r = (unsigned int)(((unsigned long long)e * magic) >> 33);
                float v = ((const float*)hoi4)[e] * ps[r] * os[r];
                if (v > THRESH) {
                    unsigned int b = (unsigned int)(v * (float)NBINS);
                    if (b > NBINS - 1) b = NBINS - 1;
                    atomicAdd(&sh[b], 1u);
                }
            }
        }
        __syncthreads();
        for (int i = threadIdx.x; i < NBINS; i += blockDim.x)
            if (sh[i]) atomicAdd(&g_hist[i], sh[i]);
    }
    grid_barrier(nblocks);

    // per-block cutoff computation (identical result everywhere)
    __shared__ unsigned int s_cut;
    if (threadIdx.x == 0) {
        unsigned int cum = 0, cut = 0;
        for (int b = NBINS - 1; b >= 0; b--) {
            cum += g_hist[b];
            if (cum >= (unsigned int)T) { cut = (unsigned int)b; break; }
        }
        s_cut = cut;
    }
    __syncthreads();
    unsigned int cut = s_cut;

    // collect candidates with bin >= cutoff
    {
        unsigned int stride = gridDim.x * blockDim.x;
        for (unsigned int q = blockIdx.x * blockDim.x + threadIdx.x; q < nvec; q += stride) {
            float4 h = hoi4[q];
            unsigned int e = q * 4u;
            unsigned int r = (unsigned int)(((unsigned long long)e * magic) >> 33);
            unsigned int c = e - r * K;
            float bs0 = ps[r] * os[r];
            float bs1 = (c + 3 >= K) ? ps[r + 1] * os[r + 1] : bs0;
            float hv[4] = {h.x, h.y, h.z, h.w};
            #pragma unroll
            for (int j = 0; j < 4; j++) {
                float v = hv[j] * ((c + (unsigned)j < K) ? bs0 : bs1);
                if (v > THRESH) {
                    unsigned int b = (unsigned int)(v * (float)NBINS);
                    if (b > NBINS - 1) b = NBINS - 1;
                    if (b >= cut) {
                        unsigned int pos = atomicAdd(&g_count2, 1u);
                        if (pos < CAP) {
                            g_cand2_val[pos] = __float_as_uint(v);
                            g_cand2_idx[pos] = e + (unsigned)j;
                        }
                    }
                }
            }
        }
        if (blockIdx.x == 0 && threadIdx.x == 0) {
            for (unsigned int e = nvec * 4u; e < N; e++) {
                unsigned int r = (unsigned int)(((unsigned long long)e * magic) >> 33);
                float v = ((const float*)hoi4)[e] * ps[r] * os[r];
                if (v > THRESH) {
                    unsigned int b = (unsigned int)(v * (float)NBINS);
                    if (b > NBINS - 1) b = NBINS - 1;
                    if (b >= cut) {
                        unsigned int pos = atomicAdd(&g_count2, 1u);
                        if (pos < CAP) {
                            g_cand2_val[pos] = __float_as_uint(v);
                            g_cand2_idx[pos] = e;
                        }
                    }
                }
            }
        }
    }
    grid_barrier(nblocks);

    if (blockIdx.x == 0) {
        unsigned int n2 = atomicAdd(&g_count2, 0u);
        if (n2 > CAP) n2 = CAP;
        rank_and_write(g_cand2_val, g_cand2_idx, n2, pb, ob, ocls, out, K, T, magic);
        if (threadIdx.x == 0) { g_count = 0; g_count2 = 0; }
    }
}

// ---------------------------------------------------------------------------
extern "C" void kernel_launch(void* const* d_in, const int* in_sizes, int n_in,
                              void* d_out, int out_size) {
    const float* pb   = (const float*)d_in[0];
    const float* ob   = (const float*)d_in[1];
    const float* ps   = (const float*)d_in[2];
    const float* os   = (const float*)d_in[3];
    const int*   ocls = (const int*)d_in[4];
    const float* hoi  = (const float*)d_in[5];

    int R = in_sizes[2];
    unsigned int N = (unsigned int)in_sizes[5];
    unsigned int K = N / (unsigned int)R;
    int T = out_size / 12;
    unsigned int nvec = N / 4u;
    unsigned long long magic = ((1ULL << 33) + K - 1) / K;  // exact e/K for e < 2^33/K

    int dev = 0, sms = 0, maxb = 0;
    cudaGetDevice(&dev);
    cudaDeviceGetAttribute(&sms, cudaDevAttrMultiProcessorCount, dev);
    cudaOccupancyMaxActiveBlocksPerMultiprocessor(&maxb, k_fused, 256, 0);
    if (maxb < 1) maxb = 1;
    unsigned int blocks = (unsigned int)(sms * maxb);   // guaranteed co-resident

    k_fused<<<blocks, 256>>>((const float4*)hoi, ps, os,
                             (const float4*)pb, (const float4*)ob, ocls,
                             (float*)d_out, nvec, N, K, magic, T, blocks);
}

// round 5
// speedup vs baseline: 3.4708x; 3.4708x over previous
#include <cuda_runtime.h>
#include <stdint.h>

#define THRESH   0.05f
#define SPEC     0.95f      // speculative cutoff; valid because hoi,ps,os < 1
#define NBINS    4096
#define CAP      65536
#define RANKMAX  4096

__device__ unsigned int g_bar;      // monotonic barrier counter (fallback only)
__device__ unsigned int g_count;    // fast-path candidates (reset at end of run)
__device__ unsigned int g_count2;   // fallback candidates  (reset at end of run)
__device__ unsigned int g_hist[NBINS];
__device__ unsigned int g_cv[CAP],  g_ci[CAP];
__device__ unsigned int g_cv2[CAP], g_ci2[CAP];

// ---------------------------------------------------------------------------
// Kernel A: stream hoi once. Stage-1 filter h > SPEC (no extra loads needed:
// v = h*ps*os <= h). Stage-2 (rare, ~5% of elements): exact v > SPEC test.
// ---------------------------------------------------------------------------
__device__ __forceinline__ void scan4(float4 h, unsigned int e, unsigned long long magic,
                                      const float* __restrict__ ps,
                                      const float* __restrict__ os) {
    float m = fmaxf(fmaxf(h.x, h.y), fmaxf(h.z, h.w));
    if (m > SPEC) {
        float hv[4] = {h.x, h.y, h.z, h.w};
        #pragma unroll
        for (int j = 0; j < 4; j++) {
            if (hv[j] > SPEC) {
                unsigned int idx = e + (unsigned)j;
                unsigned int r = (unsigned int)(((unsigned long long)idx * magic) >> 33);
                float v = hv[j] * ps[r] * os[r];
                if (v > SPEC) {
                    unsigned int pos = atomicAdd(&g_count, 1u);
                    if (pos < CAP) {
                        g_cv[pos] = __float_as_uint(v);
                        g_ci[pos] = idx;
                    }
                }
            }
        }
    }
}

__global__ void __launch_bounds__(256)
k_scan(const float4* __restrict__ hoi4,
       const float*  __restrict__ ps,
       const float*  __restrict__ os,
       unsigned int nvec, unsigned int N, unsigned long long magic) {
    unsigned int stride = gridDim.x * blockDim.x;
    unsigned int q = blockIdx.x * blockDim.x + threadIdx.x;
    for (; q + 3u * stride < nvec; q += 4u * stride) {
        float4 h0 = __ldcs(hoi4 + q);
        float4 h1 = __ldcs(hoi4 + q + stride);
        float4 h2 = __ldcs(hoi4 + q + 2u * stride);
        float4 h3 = __ldcs(hoi4 + q + 3u * stride);
        scan4(h0, q * 4u, magic, ps, os);
        scan4(h1, (q + stride) * 4u, magic, ps, os);
        scan4(h2, (q + 2u * stride) * 4u, magic, ps, os);
        scan4(h3, (q + 3u * stride) * 4u, magic, ps, os);
    }
    for (; q < nvec; q += stride) {
        float4 h = __ldcs(hoi4 + q);
        scan4(h, q * 4u, magic, ps, os);
    }
    if (blockIdx.x == 0 && threadIdx.x == 0) {
        for (unsigned int e = nvec * 4u; e < N; e++) {
            float h = ((const float*)hoi4)[e];
            if (h > SPEC) {
                unsigned int r = (unsigned int)(((unsigned long long)e * magic) >> 33);
                float v = h * ps[r] * os[r];
                if (v > SPEC) {
                    unsigned int pos = atomicAdd(&g_count, 1u);
                    if (pos < CAP) { g_cv[pos] = __float_as_uint(v); g_ci[pos] = e; }
                }
            }
        }
    }
}

// ---------------------------------------------------------------------------
// Exact rank (val desc, idx asc — jax top_k tie order) + gather.
// Output: [0,T) scores | [T,5T) pboxes | [5T,9T) oboxes | [9T,10T) ocls
//         [10T,11T) action | [11T,12T) valid
// sA/sB are shared scratch (4096 u32 each) passed in by caller.
// ---------------------------------------------------------------------------
__device__ void rank_write(const unsigned int* __restrict__ cv,
                           const unsigned int* __restrict__ ci, unsigned int n,
                           unsigned int* sA, unsigned int* sB,
                           const float4* __restrict__ pb, const float4* __restrict__ ob,
                           const int* __restrict__ ocls, float* __restrict__ out,
                           unsigned int K, int T, unsigned long long magic) {
    const unsigned int* vals = cv;
    const unsigned int* idxs = ci;
    if (n <= RANKMAX) {
        for (unsigned int i = threadIdx.x; i < n; i += blockDim.x) {
            sA[i] = cv[i];
            sB[i] = ci[i];
        }
        __syncthreads();
        vals = sA; idxs = sB;
    }
    for (unsigned int i = threadIdx.x; i < n; i += blockDim.x) {
        unsigned int vb = vals[i];
        unsigned int ix = idxs[i];
        unsigned int rank = 0;
        for (unsigned int j = 0; j < n; j++) {
            unsigned int vj = vals[j];
            rank += (vj > vb) || (vj == vb && idxs[j] < ix);  // positive floats: uint cmp == float cmp
        }
        if (rank < (unsigned int)T) {
            unsigned int pair = (unsigned int)(((unsigned long long)ix * magic) >> 33);
            unsigned int act  = ix - pair * K;
            out[rank] = __uint_as_float(vb);
            float4 p = pb[pair];
            float4 o = ob[pair];
            out[T + 4 * rank + 0] = p.x;  out[T + 4 * rank + 1] = p.y;
            out[T + 4 * rank + 2] = p.z;  out[T + 4 * rank + 3] = p.w;
            out[5 * T + 4 * rank + 0] = o.x;  out[5 * T + 4 * rank + 1] = o.y;
            out[5 * T + 4 * rank + 2] = o.z;  out[5 * T + 4 * rank + 3] = o.w;
            out[9 * T + rank]  = (float)ocls[pair];
            out[10 * T + rank] = (float)act;
            out[11 * T + rank] = 1.0f;
        }
    }
    for (int s = threadIdx.x; s < T; s += blockDim.x) {
        if ((unsigned int)s >= n) {
            out[s] = 0.0f;
            #pragma unroll
            for (int d = 0; d < 4; d++) {
                out[T + 4 * s + d] = 0.0f;
                out[5 * T + 4 * s + d] = 0.0f;
            }
            out[9 * T + s] = 0.0f;
            out[10 * T + s] = 0.0f;
            out[11 * T + s] = 0.0f;
        }
    }
}

// Grid barrier for the (never-taken) fallback path only.
__device__ __forceinline__ void grid_barrier(unsigned int nblocks) {
    __syncthreads();
    __threadfence();
    if (threadIdx.x == 0) {
        unsigned int old = atomicAdd(&g_bar, 1u);
        unsigned int target = (old / nblocks + 1u) * nblocks;
        while (atomicAdd(&g_bar, 0u) < target) __nanosleep(256);
    }
    __syncthreads();
}

// ---------------------------------------------------------------------------
// Kernel B: fast path = block 0 ranks+gathers, others exit.
// Fallback (count < T or > RANKMAX): exact hist->cutoff->collect->rank,
// using grid barriers (all blocks co-resident: grid == SM count).
// ---------------------------------------------------------------------------
__global__ void __launch_bounds__(1024)
k_rank(const float4* __restrict__ hoi4,
       const float*  __restrict__ ps, const float* __restrict__ os,
       const float4* __restrict__ pb, const float4* __restrict__ ob,
       const int*    __restrict__ ocls, float* __restrict__ out,
       unsigned int nvec, unsigned int N, unsigned int K,
       unsigned long long magic, int T, unsigned int nblocks) {
    __shared__ unsigned int sA[RANKMAX];
    __shared__ unsigned int sB[RANKMAX];

    unsigned int n = *(volatile unsigned int*)&g_count;   // uniform across blocks
    bool fast = (n >= (unsigned int)T && n <= RANKMAX);

    if (fast) {
        if (blockIdx.x == 0) {
            rank_write(g_cv, g_ci, n, sA, sB, pb, ob, ocls, out, K, T, magic);
            __syncthreads();
            if (threadIdx.x == 0) { g_count = 0; g_count2 = 0; }
        }
        return;
    }

    // ===== exact fallback =====
    {   // zero global hist
        unsigned int stride = gridDim.x * blockDim.x;
        for (unsigned int i = blockIdx.x * blockDim.x + threadIdx.x; i < NBINS; i += stride)
            g_hist[i] = 0;
    }
    grid_barrier(nblocks);

    {   // shared-privatized histogram of v > THRESH (reuse sA as hist)
        for (int i = threadIdx.x; i < NBINS; i += blockDim.x) sA[i] = 0;
        __syncthreads();
        unsigned int stride = gridDim.x * blockDim.x;
        for (unsigned int q = blockIdx.x * blockDim.x + threadIdx.x; q < nvec; q += stride) {
            float4 h = hoi4[q];
            unsigned int e = q * 4u;
            float hv[4] = {h.x, h.y, h.z, h.w};
            #pragma unroll
            for (int j = 0; j < 4; j++) {
                unsigned int idx = e + (unsigned)j;
                unsigned int r = (unsigned int)(((unsigned long long)idx * magic) >> 33);
                float v = hv[j] * ps[r] * os[r];
                if (v > THRESH) {
                    unsigned int b = (unsigned int)(v * (float)NBINS);
                    if (b > NBINS - 1) b = NBINS - 1;
                    atomicAdd(&sA[b], 1u);
                }
            }
        }
        if (blockIdx.x == 0 && threadIdx.x == 0) {
            for (unsigned int e = nvec * 4u; e < N; e++) {
                unsigned int r = (unsigned int)(((unsigned long long)e * magic) >> 33);
                float v = ((const float*)hoi4)[e] * ps[r] * os[r];
                if (v > THRESH) {
                    unsigned int b = (unsigned int)(v * (float)NBINS);
                    if (b > NBINS - 1) b = NBINS - 1;
                    atomicAdd(&sA[b], 1u);
                }
            }
        }
        __syncthreads();
        for (int i = threadIdx.x; i < NBINS; i += blockDim.x)
            if (sA[i]) atomicAdd(&g_hist[i], sA[i]);
    }
    grid_barrier(nblocks);

    __shared__ unsigned int s_cut;
    if (threadIdx.x == 0) {
        unsigned int cum = 0, cut = 0;
        for (int b = NBINS - 1; b >= 0; b--) {
            cum += g_hist[b];
            if (cum >= (unsigned int)T) { cut = (unsigned int)b; break; }
        }
        s_cut = cut;
    }
    __syncthreads();
    unsigned int cut = s_cut;

    {   // collect candidates with bin >= cutoff
        unsigned int stride = gridDim.x * blockDim.x;
        for (unsigned int q = blockIdx.x * blockDim.x + threadIdx.x; q < nvec; q += stride) {
            float4 h = hoi4[q];
            unsigned int e = q * 4u;
            float hv[4] = {h.x, h.y, h.z, h.w};
            #pragma unroll
            for (int j = 0; j < 4; j++) {
                unsigned int idx = e + (unsigned)j;
                unsigned int r = (unsigned int)(((unsigned long long)idx * magic) >> 33);
                float v = hv[j] * ps[r] * os[r];
                if (v > THRESH) {
                    unsigned int b = (unsigned int)(v * (float)NBINS);
                    if (b > NBINS - 1) b = NBINS - 1;
                    if (b >= cut) {
                        unsigned int pos = atomicAdd(&g_count2, 1u);
                        if (pos < CAP) {
                            g_cv2[pos] = __float_as_uint(v);
                            g_ci2[pos] = idx;
                        }
                    }
                }
            }
        }
        if (blockIdx.x == 0 && threadIdx.x == 0) {
            for (unsigned int e = nvec * 4u; e < N; e++) {
                unsigned int r = (unsigned int)(((unsigned long long)e * magic) >> 33);
                float v = ((const float*)hoi4)[e] * ps[r] * os[r];
                if (v > THRESH) {
                    unsigned int b = (unsigned int)(v * (float)NBINS);
                    if (b > NBINS - 1) b = NBINS - 1;
                    if (b >= cut) {
                        unsigned int pos = atomicAdd(&g_count2, 1u);
                        if (pos < CAP) {
                            g_cv2[pos] = __float_as_uint(v);
                            g_ci2[pos] = e;
                        }
                    }
                }
            }
        }
    }
    grid_barrier(nblocks);

    if (blockIdx.x == 0) {
        unsigned int n2 = *(volatile unsigned int*)&g_count2;
        if (n2 > CAP) n2 = CAP;
        __syncthreads();
        rank_write(g_cv2, g_ci2, n2, sA, sB, pb, ob, ocls, out, K, T, magic);
        __syncthreads();
        if (threadIdx.x == 0) { g_count = 0; g_count2 = 0; }
    }
}

// ---------------------------------------------------------------------------
extern "C" void kernel_launch(void* const* d_in, const int* in_sizes, int n_in,
                              void* d_out, int out_size) {
    const float* pb   = (const float*)d_in[0];
    const float* ob   = (const float*)d_in[1];
    const float* ps   = (const float*)d_in[2];
    const float* os   = (const float*)d_in[3];
    const int*   ocls = (const int*)d_in[4];
    const float* hoi  = (const float*)d_in[5];

    int R = in_sizes[2];
    unsigned int N = (unsigned int)in_sizes[5];
    unsigned int K = N / (unsigned int)R;
    int T = out_size / 12;
    unsigned int nvec = N / 4u;
    unsigned long long magic = ((1ULL << 33) + K - 1) / K;  // exact e/K, e < 2^33/K

    int dev = 0, sms = 148;
    cudaGetDevice(&dev);
    cudaDeviceGetAttribute(&sms, cudaDevAttrMultiProcessorCount, dev);

    unsigned int scan_blocks = (unsigned int)(sms * 8);
    k_scan<<<scan_blocks, 256>>>((const float4*)hoi, ps, os, nvec, N, magic);

    unsigned int fb_blocks = (unsigned int)sms;   // co-resident (1024 thr => <=2/SM)
    k_rank<<<fb_blocks, 1024>>>((const float4*)hoi, ps, os,
                                (const float4*)pb, (const float4*)ob, ocls,
                                (float*)d_out, nvec, N, K, magic, T, fb_blocks);
}

// round 6
// speedup vs baseline: 3.6793x; 1.0601x over previous
#include <cuda_runtime.h>
#include <stdint.h>

#define THRESH   0.05f
#define SPEC     0.95f      // speculative cutoff; valid because hoi,ps,os < 1
#define NBINS    4096
#define CAP      65536
#define RANKMAX  4096

__device__ unsigned int g_bar;      // monotonic barrier counter (fallback only)
__device__ unsigned int g_done;     // monotonic last-out counter (k_rank)
__device__ unsigned int g_count;    // fast-path candidates (reset by last block out)
__device__ unsigned int g_count2;   // fallback candidates  (reset by last block out)
__device__ unsigned int g_hist[NBINS];
__device__ unsigned int g_cv[CAP],  g_ci[CAP];
__device__ unsigned int g_cv2[CAP], g_ci2[CAP];

// ---------------------------------------------------------------------------
// Kernel A: stream hoi once. Stage-1 filter h > SPEC (free: v = h*ps*os <= h).
// Stage-2 (~5% of elements): exact v > SPEC test with the two scalar loads.
// ---------------------------------------------------------------------------
__device__ __forceinline__ void scan4(float4 h, unsigned int e, unsigned long long magic,
                                      const float* __restrict__ ps,
                                      const float* __restrict__ os) {
    float m = fmaxf(fmaxf(h.x, h.y), fmaxf(h.z, h.w));
    if (m > SPEC) {
        float hv[4] = {h.x, h.y, h.z, h.w};
        #pragma unroll
        for (int j = 0; j < 4; j++) {
            if (hv[j] > SPEC) {
                unsigned int idx = e + (unsigned)j;
                unsigned int r = (unsigned int)(((unsigned long long)idx * magic) >> 33);
                float v = hv[j] * ps[r] * os[r];
                if (v > SPEC) {
                    unsigned int pos = atomicAdd(&g_count, 1u);
                    if (pos < CAP) {
                        g_cv[pos] = __float_as_uint(v);
                        g_ci[pos] = idx;
                    }
                }
            }
        }
    }
}

__global__ void __launch_bounds__(256)
k_scan(const float4* __restrict__ hoi4,
       const float*  __restrict__ ps,
       const float*  __restrict__ os,
       unsigned int nvec, unsigned int N, unsigned long long magic) {
    unsigned int stride = gridDim.x * blockDim.x;
    unsigned int q = blockIdx.x * blockDim.x + threadIdx.x;
    for (; q + 3u * stride < nvec; q += 4u * stride) {
        float4 h0 = __ldcs(hoi4 + q);
        float4 h1 = __ldcs(hoi4 + q + stride);
        float4 h2 = __ldcs(hoi4 + q + 2u * stride);
        float4 h3 = __ldcs(hoi4 + q + 3u * stride);
        scan4(h0, q * 4u, magic, ps, os);
        scan4(h1, (q + stride) * 4u, magic, ps, os);
        scan4(h2, (q + 2u * stride) * 4u, magic, ps, os);
        scan4(h3, (q + 3u * stride) * 4u, magic, ps, os);
    }
    for (; q < nvec; q += stride) {
        float4 h = __ldcs(hoi4 + q);
        scan4(h, q * 4u, magic, ps, os);
    }
    if (blockIdx.x == 0 && threadIdx.x == 0) {
        for (unsigned int e = nvec * 4u; e < N; e++) {
            float h = ((const float*)hoi4)[e];
            if (h > SPEC) {
                unsigned int r = (unsigned int)(((unsigned long long)e * magic) >> 33);
                float v = h * ps[r] * os[r];
                if (v > SPEC) {
                    unsigned int pos = atomicAdd(&g_count, 1u);
                    if (pos < CAP) { g_cv[pos] = __float_as_uint(v); g_ci[pos] = e; }
                }
            }
        }
    }
}

// ---------------------------------------------------------------------------
// Write one ranked detection into the flat output:
//   [0,T) scores | [T,5T) pboxes | [5T,9T) oboxes | [9T,10T) ocls
//   [10T,11T) action | [11T,12T) valid
// ---------------------------------------------------------------------------
__device__ __forceinline__ void write_det(unsigned int rank, unsigned int vb,
                                          unsigned int ix,
                                          const float4* __restrict__ pb,
                                          const float4* __restrict__ ob,
                                          const int* __restrict__ ocls,
                                          float* __restrict__ out,
                                          unsigned int K, int T,
                                          unsigned long long magic) {
    unsigned int pair = (unsigned int)(((unsigned long long)ix * magic) >> 33);
    unsigned int act  = ix - pair * K;
    out[rank] = __uint_as_float(vb);
    float4 p = pb[pair];
    float4 o = ob[pair];
    out[T + 4 * rank + 0] = p.x;  out[T + 4 * rank + 1] = p.y;
    out[T + 4 * rank + 2] = p.z;  out[T + 4 * rank + 3] = p.w;
    out[5 * T + 4 * rank + 0] = o.x;  out[5 * T + 4 * rank + 1] = o.y;
    out[5 * T + 4 * rank + 2] = o.z;  out[5 * T + 4 * rank + 3] = o.w;
    out[9 * T + rank]  = (float)ocls[pair];
    out[10 * T + rank] = (float)act;
    out[11 * T + rank] = 1.0f;
}

// Grid barrier for the (never-taken) fallback path only.
__device__ __forceinline__ void grid_barrier(unsigned int nblocks) {
    __syncthreads();
    __threadfence();
    if (threadIdx.x == 0) {
        unsigned int old = atomicAdd(&g_bar, 1u);
        unsigned int target = (old / nblocks + 1u) * nblocks;
        while (atomicAdd(&g_bar, 0u) < target) __nanosleep(256);
    }
    __syncthreads();
}

// ---------------------------------------------------------------------------
// Kernel B: fast path = ALL blocks rank in parallel (each holds the full
// candidate set in shared, ranks a disjoint i-slice, writes its winners).
// Fallback (count < T or > RANKMAX): exact hist->cutoff->collect->rank.
// Counter reset: last-block-out on monotonic g_done (race-free across replays).
// ---------------------------------------------------------------------------
__global__ void __launch_bounds__(1024)
k_rank(const float4* __restrict__ hoi4,
       const float*  __restrict__ ps, const float* __restrict__ os,
       const float4* __restrict__ pb, const float4* __restrict__ ob,
       const int*    __restrict__ ocls, float* __restrict__ out,
       unsigned int nvec, unsigned int N, unsigned int K,
       unsigned long long magic, int T, unsigned int nblocks) {
    __shared__ unsigned int sA[RANKMAX];
    __shared__ unsigned int sB[RANKMAX];

    unsigned int n = *(volatile unsigned int*)&g_count;   // uniform across blocks
    bool fast = (n >= (unsigned int)T && n <= RANKMAX);

    if (fast) {
        unsigned int G = gridDim.x;
        unsigned int chunk = (n + G - 1u) / G;
        unsigned int i0 = blockIdx.x * chunk;
        unsigned int i1 = i0 + chunk; if (i1 > n) i1 = n;
        if (i0 < n) {
            for (unsigned int i = threadIdx.x; i < n; i += blockDim.x) {
                sA[i] = g_cv[i];
                sB[i] = g_ci[i];
            }
            __syncthreads();
            for (unsigned int i = i0 + threadIdx.x; i < i1; i += blockDim.x) {
                unsigned int vb = sA[i];
                unsigned int ix = sB[i];
                unsigned int rank = 0;
                for (unsigned int j = 0; j < n; j++) {
                    unsigned int vj = sA[j];
                    // positive floats: uint compare == float compare
                    rank += (vj > vb) || (vj == vb && sB[j] < ix);
                }
                if (rank < (unsigned int)T)
                    write_det(rank, vb, ix, pb, ob, ocls, out, K, T, magic);
            }
        }
    } else {
        // ===== exact fallback (all blocks take this branch uniformly) =====
        {   // zero global hist
            unsigned int stride = gridDim.x * blockDim.x;
            for (unsigned int i = blockIdx.x * blockDim.x + threadIdx.x; i < NBINS; i += stride)
                g_hist[i] = 0;
        }
        grid_barrier(nblocks);

        {   // shared-privatized histogram of v > THRESH (reuse sA as hist)
            for (int i = threadIdx.x; i < NBINS; i += blockDim.x) sA[i] = 0;
            __syncthreads();
            unsigned int stride = gridDim.x * blockDim.x;
            for (unsigned int q = blockIdx.x * blockDim.x + threadIdx.x; q < nvec; q += stride) {
                float4 h = hoi4[q];
                unsigned int e = q * 4u;
                float hv[4] = {h.x, h.y, h.z, h.w};
                #pragma unroll
                for (int j = 0; j < 4; j++) {
                    unsigned int idx = e + (unsigned)j;
                    unsigned int r = (unsigned int)(((unsigned long long)idx * magic) >> 33);
                    float v = hv[j] * ps[r] * os[r];
                    if (v > THRESH) {
                        unsigned int b = (unsigned int)(v * (float)NBINS);
                        if (b > NBINS - 1) b = NBINS - 1;
                        atomicAdd(&sA[b], 1u);
                    }
                }
            }
            if (blockIdx.x == 0 && threadIdx.x == 0) {
                for (unsigned int e = nvec * 4u; e < N; e++) {
                    unsigned int r = (unsigned int)(((unsigned long long)e * magic) >> 33);
                    float v = ((const float*)hoi4)[e] * ps[r] * os[r];
                    if (v > THRESH) {
                        unsigned int b = (unsigned int)(v * (float)NBINS);
                        if (b > NBINS - 1) b = NBINS - 1;
                        atomicAdd(&sA[b], 1u);
                    }
                }
            }
            __syncthreads();
            for (int i = threadIdx.x; i < NBINS; i += blockDim.x)
                if (sA[i]) atomicAdd(&g_hist[i], sA[i]);
        }
        grid_barrier(nblocks);

        __shared__ unsigned int s_cut;
        if (threadIdx.x == 0) {
            unsigned int cum = 0, cut = 0;
            for (int b = NBINS - 1; b >= 0; b--) {
                cum += g_hist[b];
                if (cum >= (unsigned int)T) { cut = (unsigned int)b; break; }
            }
            s_cut = cut;
        }
        __syncthreads();
        unsigned int cut = s_cut;

        {   // collect candidates with bin >= cutoff
            unsigned int stride = gridDim.x * blockDim.x;
            for (unsigned int q = blockIdx.x * blockDim.x + threadIdx.x; q < nvec; q += stride) {
                float4 h = hoi4[q];
                unsigned int e = q * 4u;
                float hv[4] = {h.x, h.y, h.z, h.w};
                #pragma unroll
                for (int j = 0; j < 4; j++) {
                    unsigned int idx = e + (unsigned)j;
                    unsigned int r = (unsigned int)(((unsigned long long)idx * magic) >> 33);
                    float v = hv[j] * ps[r] * os[r];
                    if (v > THRESH) {
                        unsigned int b = (unsigned int)(v * (float)NBINS);
                        if (b > NBINS - 1) b = NBINS - 1;
                        if (b >= cut) {
                            unsigned int pos = atomicAdd(&g_count2, 1u);
                            if (pos < CAP) {
                                g_cv2[pos] = __float_as_uint(v);
                                g_ci2[pos] = idx;
                            }
                        }
                    }
                }
            }
            if (blockIdx.x == 0 && threadIdx.x == 0) {
                for (unsigned int e = nvec * 4u; e < N; e++) {
                    unsigned int r = (unsigned int)(((unsigned long long)e * magic) >> 33);
                    float v = ((const float*)hoi4)[e] * ps[r] * os[r];
                    if (v > THRESH) {
                        unsigned int b = (unsigned int)(v * (float)NBINS);
                        if (b > NBINS - 1) b = NBINS - 1;
                        if (b >= cut) {
                            unsigned int pos = atomicAdd(&g_count2, 1u);
                            if (pos < CAP) {
                                g_cv2[pos] = __float_as_uint(v);
                                g_ci2[pos] = e;
                            }
                        }
                    }
                }
            }
        }
        grid_barrier(nblocks);

        // parallel exact rank over collected candidates
        unsigned int n2 = *(volatile unsigned int*)&g_count2;
        if (n2 > RANKMAX) n2 = RANKMAX;  // cutoff guarantees >= T candidates fit when possible
        unsigned int G = gridDim.x;
        unsigned int chunk = (n2 + G - 1u) / G;
        unsigned int i0 = blockIdx.x * chunk;
        unsigned int i1 = i0 + chunk; if (i1 > n2) i1 = n2;
        __syncthreads();
        if (n2 > 0 && i0 < n2) {
            for (unsigned int i = threadIdx.x; i < n2; i += blockDim.x) {
                sA[i] = g_cv2[i];
                sB[i] = g_ci2[i];
            }
            __syncthreads();
            for (unsigned int i = i0 + threadIdx.x; i < i1; i += blockDim.x) {
                unsigned int vb = sA[i];
                unsigned int ix = sB[i];
                unsigned int rank = 0;
                for (unsigned int j = 0; j < n2; j++) {
                    unsigned int vj = sA[j];
                    rank += (vj > vb) || (vj == vb && sB[j] < ix);
                }
                if (rank < (unsigned int)T)
                    write_det(rank, vb, ix, pb, ob, ocls, out, K, T, magic);
            }
        }
        // zero-pad unfilled slots (n2 < T): block 0
        if (blockIdx.x == 0) {
            for (int s = threadIdx.x; s < T; s += blockDim.x) {
                if ((unsigned int)s >= n2) {
                    out[s] = 0.0f;
                    #pragma unroll
                    for (int d = 0; d < 4; d++) {
                        out[T + 4 * s + d] = 0.0f;
                        out[5 * T + 4 * s + d] = 0.0f;
                    }
                    out[9 * T + s] = 0.0f;
                    out[10 * T + s] = 0.0f;
                    out[11 * T + s] = 0.0f;
                }
            }
        }
    }

    // ---- last-block-out counter reset (race-free: every block's read of
    // g_count precedes its arrival; reset fires only at the final arrival) ----
    __syncthreads();
    __threadfence();
    if (threadIdx.x == 0) {
        unsigned int old = atomicAdd(&g_done, 1u);
        if ((old % nblocks) == nblocks - 1u) {
            g_count = 0;
            g_count2 = 0;
        }
    }
}

// ---------------------------------------------------------------------------
extern "C" void kernel_launch(void* const* d_in, const int* in_sizes, int n_in,
                              void* d_out, int out_size) {
    const float* pb   = (const float*)d_in[0];
    const float* ob   = (const float*)d_in[1];
    const float* ps   = (const float*)d_in[2];
    const float* os   = (const float*)d_in[3];
    const int*   ocls = (const int*)d_in[4];
    const float* hoi  = (const float*)d_in[5];

    int R = in_sizes[2];
    unsigned int N = (unsigned int)in_sizes[5];
    unsigned int K = N / (unsigned int)R;
    int T = out_size / 12;
    unsigned int nvec = N / 4u;
    unsigned long long magic = ((1ULL << 33) + K - 1) / K;  // exact e/K, e < 2^33/K

    int dev = 0, sms = 148;
    cudaGetDevice(&dev);
    cudaDeviceGetAttribute(&sms, cudaDevAttrMultiProcessorCount, dev);

    unsigned int scan_blocks = (unsigned int)(sms * 8);
    k_scan<<<scan_blocks, 256>>>((const float4*)hoi, ps, os, nvec, N, magic);

    unsigned int fb_blocks = (unsigned int)sms;   // co-resident (1024 thr => <=2/SM)
    k_rank<<<fb_blocks, 1024>>>((const float4*)hoi, ps, os,
                                (const float4*)pb, (const float4*)ob, ocls,
                                (float*)d_out, nvec, N, K, magic, T, fb_blocks);
}

// round 7
// speedup vs baseline: 6.1678x; 1.6764x over previous
#include <cuda_runtime.h>
#include <stdint.h>

#define THRESH   0.05f
#define SPEC     0.95f      // speculative cutoff; valid because hoi,ps,os < 1
#define NBINS    4096
#define CAP      65536
#define RANKMAX  4096

__device__ unsigned int g_bar;      // monotonic barrier counter (fallback only)
__device__ unsigned int g_done;     // monotonic last-out counter (k_rank)
__device__ unsigned int g_count;    // fast-path candidates (reset by last block out)
__device__ unsigned int g_count2;   // fallback candidates  (reset by last block out)
__device__ unsigned int g_hist[NBINS];
__device__ unsigned int g_cv[CAP],  g_ci[CAP];
__device__ unsigned int g_cv2[CAP], g_ci2[CAP];

// key packs (value, index) so that key_j > key_i  <=>  j ranks ahead of i
// (value desc, index asc — matches jax.lax.top_k). Values positive floats:
// uint compare == float compare. Keys are unique (indices unique).
__device__ __forceinline__ unsigned long long mk_key(unsigned int vbits, unsigned int idx) {
    return ((unsigned long long)vbits << 32) | (unsigned long long)(0xFFFFFFFFu - idx);
}

// ---------------------------------------------------------------------------
// Kernel A: stream hoi once. Stage-1 filter h > SPEC (free: v = h*ps*os <= h).
// Stage-2 (~5% of elements): exact v > SPEC test with the two scalar loads.
// ---------------------------------------------------------------------------
__device__ __forceinline__ void scan4(float4 h, unsigned int e, unsigned long long magic,
                                      const float* __restrict__ ps,
                                      const float* __restrict__ os) {
    float m = fmaxf(fmaxf(h.x, h.y), fmaxf(h.z, h.w));
    if (m > SPEC) {
        float hv[4] = {h.x, h.y, h.z, h.w};
        #pragma unroll
        for (int j = 0; j < 4; j++) {
            if (hv[j] > SPEC) {
                unsigned int idx = e + (unsigned)j;
                unsigned int r = (unsigned int)(((unsigned long long)idx * magic) >> 33);
                float v = hv[j] * ps[r] * os[r];
                if (v > SPEC) {
                    unsigned int pos = atomicAdd(&g_count, 1u);
                    if (pos < CAP) {
                        g_cv[pos] = __float_as_uint(v);
                        g_ci[pos] = idx;
                    }
                }
            }
        }
    }
}

__global__ void __launch_bounds__(256)
k_scan(const float4* __restrict__ hoi4,
       const float*  __restrict__ ps,
       const float*  __restrict__ os,
       unsigned int nvec, unsigned int N, unsigned long long magic) {
    unsigned int stride = gridDim.x * blockDim.x;
    unsigned int q = blockIdx.x * blockDim.x + threadIdx.x;
    for (; q + 3u * stride < nvec; q += 4u * stride) {
        float4 h0 = __ldcs(hoi4 + q);
        float4 h1 = __ldcs(hoi4 + q + stride);
        float4 h2 = __ldcs(hoi4 + q + 2u * stride);
        float4 h3 = __ldcs(hoi4 + q + 3u * stride);
        scan4(h0, q * 4u, magic, ps, os);
        scan4(h1, (q + stride) * 4u, magic, ps, os);
        scan4(h2, (q + 2u * stride) * 4u, magic, ps, os);
        scan4(h3, (q + 3u * stride) * 4u, magic, ps, os);
    }
    for (; q < nvec; q += stride) {
        float4 h = __ldcs(hoi4 + q);
        scan4(h, q * 4u, magic, ps, os);
    }
    if (blockIdx.x == 0 && threadIdx.x == 0) {
        for (unsigned int e = nvec * 4u; e < N; e++) {
            float h = ((const float*)hoi4)[e];
            if (h > SPEC) {
                unsigned int r = (unsigned int)(((unsigned long long)e * magic) >> 33);
                float v = h * ps[r] * os[r];
                if (v > SPEC) {
                    unsigned int pos = atomicAdd(&g_count, 1u);
                    if (pos < CAP) { g_cv[pos] = __float_as_uint(v); g_ci[pos] = e; }
                }
            }
        }
    }
}

// ---------------------------------------------------------------------------
// Write one ranked detection into the flat output:
//   [0,T) scores | [T,5T) pboxes | [5T,9T) oboxes | [9T,10T) ocls
//   [10T,11T) action | [11T,12T) valid
// ---------------------------------------------------------------------------
__device__ __forceinline__ void write_det(unsigned int rank, unsigned int vb,
                                          unsigned int ix,
                                          const float4* __restrict__ pb,
                                          const float4* __restrict__ ob,
                                          const int* __restrict__ ocls,
                                          float* __restrict__ out,
                                          unsigned int K, int T,
                                          unsigned long long magic) {
    unsigned int pair = (unsigned int)(((unsigned long long)ix * magic) >> 33);
    unsigned int act  = ix - pair * K;
    out[rank] = __uint_as_float(vb);
    float4 p = pb[pair];
    float4 o = ob[pair];
    out[T + 4 * rank + 0] = p.x;  out[T + 4 * rank + 1] = p.y;
    out[T + 4 * rank + 2] = p.z;  out[T + 4 * rank + 3] = p.w;
    out[5 * T + 4 * rank + 0] = o.x;  out[5 * T + 4 * rank + 1] = o.y;
    out[5 * T + 4 * rank + 2] = o.z;  out[5 * T + 4 * rank + 3] = o.w;
    out[9 * T + rank]  = (float)ocls[pair];
    out[10 * T + rank] = (float)act;
    out[11 * T + rank] = 1.0f;
}

// Count keys strictly greater than kb among sK[0..n). Unrolled x8: the 8
// LDS.64 per batch are independent -> latency pipelined (the R6 bottleneck
// was this loop as a serial dependent chain).
__device__ __forceinline__ unsigned int rank_of(const unsigned long long* sK,
                                                unsigned int n,
                                                unsigned long long kb) {
    unsigned int rank = 0;
    unsigned int j = 0;
    for (; j + 8u <= n; j += 8u) {
        unsigned int a = 0;
        #pragma unroll
        for (int t = 0; t < 8; t++) a += (sK[j + t] > kb);
        rank += a;
    }
    for (; j < n; j++) rank += (sK[j] > kb);
    return rank;
}

// Grid barrier for the (never-taken) fallback path only.
__device__ __forceinline__ void grid_barrier(unsigned int nblocks) {
    __syncthreads();
    __threadfence();
    if (threadIdx.x == 0) {
        unsigned int old = atomicAdd(&g_bar, 1u);
        unsigned int target = (old / nblocks + 1u) * nblocks;
        while (atomicAdd(&g_bar, 0u) < target) __nanosleep(256);
    }
    __syncthreads();
}

// ---------------------------------------------------------------------------
// Kernel B: fast path = all blocks hold the packed key set in shared and rank
// disjoint i-slices with the unrolled counter. Fallback = exact hist ->
// cutoff -> collect -> parallel rank. Reset = last-block-out on g_done.
// ---------------------------------------------------------------------------
__global__ void __launch_bounds__(1024)
k_rank(const float4* __restrict__ hoi4,
       const float*  __restrict__ ps, const float* __restrict__ os,
       const float4* __restrict__ pb, const float4* __restrict__ ob,
       const int*    __restrict__ ocls, float* __restrict__ out,
       unsigned int nvec, unsigned int N, unsigned int K,
       unsigned long long magic, int T, unsigned int nblocks) {
    __shared__ unsigned long long sK[RANKMAX];     // 32KB

    unsigned int n = *(volatile unsigned int*)&g_count;   // uniform across blocks
    bool fast = (n >= (unsigned int)T && n <= RANKMAX);

    if (fast) {
        unsigned int G = gridDim.x;
        unsigned int chunk = (n + G - 1u) / G;
        unsigned int i0 = blockIdx.x * chunk;
        unsigned int i1 = i0 + chunk; if (i1 > n) i1 = n;
        if (i0 < n) {
            for (unsigned int i = threadIdx.x; i < n; i += blockDim.x)
                sK[i] = mk_key(g_cv[i], g_ci[i]);
            __syncthreads();
            for (unsigned int i = i0 + threadIdx.x; i < i1; i += blockDim.x) {
                unsigned long long kb = sK[i];
                unsigned int rank = rank_of(sK, n, kb);
                if (rank < (unsigned int)T) {
                    unsigned int vb = (unsigned int)(kb >> 32);
                    unsigned int ix = 0xFFFFFFFFu - (unsigned int)(kb & 0xFFFFFFFFu);
                    write_det(rank, vb, ix, pb, ob, ocls, out, K, T, magic);
                }
            }
        }
    } else {
        // ===== exact fallback (all blocks take this branch uniformly) =====
        unsigned int* sh = (unsigned int*)sK;   // reuse shared as histogram
        {   // zero global hist
            unsigned int stride = gridDim.x * blockDim.x;
            for (unsigned int i = blockIdx.x * blockDim.x + threadIdx.x; i < NBINS; i += stride)
                g_hist[i] = 0;
        }
        grid_barrier(nblocks);

        {   // shared-privatized histogram of v > THRESH
            for (int i = threadIdx.x; i < NBINS; i += blockDim.x) sh[i] = 0;
            __syncthreads();
            unsigned int stride = gridDim.x * blockDim.x;
            for (unsigned int q = blockIdx.x * blockDim.x + threadIdx.x; q < nvec; q += stride) {
                float4 h = hoi4[q];
                unsigned int e = q * 4u;
                float hv[4] = {h.x, h.y, h.z, h.w};
                #pragma unroll
                for (int j = 0; j < 4; j++) {
                    unsigned int idx = e + (unsigned)j;
                    unsigned int r = (unsigned int)(((unsigned long long)idx * magic) >> 33);
                    float v = hv[j] * ps[r] * os[r];
                    if (v > THRESH) {
                        unsigned int b = (unsigned int)(v * (float)NBINS);
                        if (b > NBINS - 1) b = NBINS - 1;
                        atomicAdd(&sh[b], 1u);
                    }
                }
            }
            if (blockIdx.x == 0 && threadIdx.x == 0) {
                for (unsigned int e = nvec * 4u; e < N; e++) {
                    unsigned int r = (unsigned int)(((unsigned long long)e * magic) >> 33);
                    float v = ((const float*)hoi4)[e] * ps[r] * os[r];
                    if (v > THRESH) {
                        unsigned int b = (unsigned int)(v * (float)NBINS);
                        if (b > NBINS - 1) b = NBINS - 1;
                        atomicAdd(&sh[b], 1u);
                    }
                }
            }
            __syncthreads();
            for (int i = threadIdx.x; i < NBINS; i += blockDim.x)
                if (sh[i]) atomicAdd(&g_hist[i], sh[i]);
        }
        grid_barrier(nblocks);

        __shared__ unsigned int s_cut;
        if (threadIdx.x == 0) {
            unsigned int cum = 0, cut = 0;
            for (int b = NBINS - 1; b >= 0; b--) {
                cum += g_hist[b];
                if (cum >= (unsigned int)T) { cut = (unsigned int)b; break; }
            }
            s_cut = cut;
        }
        __syncthreads();
        unsigned int cut = s_cut;

        {   // collect candidates with bin >= cutoff
            unsigned int stride = gridDim.x * blockDim.x;
            for (unsigned int q = blockIdx.x * blockDim.x + threadIdx.x; q < nvec; q += stride) {
                float4 h = hoi4[q];
                unsigned int e = q * 4u;
                float hv[4] = {h.x, h.y, h.z, h.w};
                #pragma unroll
                for (int j = 0; j < 4; j++) {
                    unsigned int idx = e + (unsigned)j;
                    unsigned int r = (unsigned int)(((unsigned long long)idx * magic) >> 33);
                    float v = hv[j] * ps[r] * os[r];
                    if (v > THRESH) {
                        unsigned int b = (unsigned int)(v * (float)NBINS);
                        if (b > NBINS - 1) b = NBINS - 1;
                        if (b >= cut) {
                            unsigned int pos = atomicAdd(&g_count2, 1u);
                            if (pos < CAP) {
                                g_cv2[pos] = __float_as_uint(v);
                                g_ci2[pos] = idx;
                            }
                        }
                    }
                }
            }
            if (blockIdx.x == 0 && threadIdx.x == 0) {
                for (unsigned int e = nvec * 4u; e < N; e++) {
                    unsigned int r = (unsigned int)(((unsigned long long)e * magic) >> 33);
                    float v = ((const float*)hoi4)[e] * ps[r] * os[r];
                    if (v > THRESH) {
                        unsigned int b = (unsigned int)(v * (float)NBINS);
                        if (b > NBINS - 1) b = NBINS - 1;
                        if (b >= cut) {
                            unsigned int pos = atomicAdd(&g_count2, 1u);
                            if (pos < CAP) {
                                g_cv2[pos] = __float_as_uint(v);
                                g_ci2[pos] = e;
                            }
                        }
                    }
                }
            }
        }
        grid_barrier(nblocks);

        // parallel exact rank over collected candidates
        unsigned int n2 = *(volatile unsigned int*)&g_count2;
        if (n2 > RANKMAX) n2 = RANKMAX;
        unsigned int G = gridDim.x;
        unsigned int chunk = (n2 + G - 1u) / G;
        unsigned int i0 = blockIdx.x * chunk;
        unsigned int i1 = i0 + chunk; if (i1 > n2) i1 = n2;
        __syncthreads();
        if (n2 > 0 && i0 < n2) {
            for (unsigned int i = threadIdx.x; i < n2; i += blockDim.x)
                sK[i] = mk_key(g_cv2[i], g_ci2[i]);
            __syncthreads();
            for (unsigned int i = i0 + threadIdx.x; i < i1; i += blockDim.x) {
                unsigned long long kb = sK[i];
                unsigned int rank = rank_of(sK, n2, kb);
                if (rank < (unsigned int)T) {
                    unsigned int vb = (unsigned int)(kb >> 32);
                    unsigned int ix = 0xFFFFFFFFu - (unsigned int)(kb & 0xFFFFFFFFu);
                    write_det(rank, vb, ix, pb, ob, ocls, out, K, T, magic);
                }
            }
        }
        // zero-pad unfilled slots (n2 < T): block 0
        if (blockIdx.x == 0) {
            for (int s = threadIdx.x; s < T; s += blockDim.x) {
                if ((unsigned int)s >= n2) {
                    out[s] = 0.0f;
                    #pragma unroll
                    for (int d = 0; d < 4; d++) {
                        out[T + 4 * s + d] = 0.0f;
                        out[5 * T + 4 * s + d] = 0.0f;
                    }
                    out[9 * T + s] = 0.0f;
                    out[10 * T + s] = 0.0f;
                    out[11 * T + s] = 0.0f;
                }
            }
        }
    }

    // ---- last-block-out counter reset (race-free: every block's read of
    // g_count precedes its arrival; reset fires only at the final arrival) ----
    __syncthreads();
    __threadfence();
    if (threadIdx.x == 0) {
        unsigned int old = atomicAdd(&g_done, 1u);
        if ((old % nblocks) == nblocks - 1u) {
            g_count = 0;
            g_count2 = 0;
        }
    }
}

// ---------------------------------------------------------------------------
extern "C" void kernel_launch(void* const* d_in, const int* in_sizes, int n_in,
                              void* d_out, int out_size) {
    const float* pb   = (const float*)d_in[0];
    const float* ob   = (const float*)d_in[1];
    const float* ps   = (const float*)d_in[2];
    const float* os   = (const float*)d_in[3];
    const int*   ocls = (const int*)d_in[4];
    const float* hoi  = (const float*)d_in[5];

    int R = in_sizes[2];
    unsigned int N = (unsigned int)in_sizes[5];
    unsigned int K = N / (unsigned int)R;
    int T = out_size / 12;
    unsigned int nvec = N / 4u;
    unsigned long long magic = ((1ULL << 33) + K - 1) / K;  // exact e/K, e < 2^33/K

    int dev = 0, sms = 148;
    cudaGetDevice(&dev);
    cudaDeviceGetAttribute(&sms, cudaDevAttrMultiProcessorCount, dev);

    unsigned int scan_blocks = (unsigned int)(sms * 8);
    k_scan<<<scan_blocks, 256>>>((const float4*)hoi, ps, os, nvec, N, magic);

    unsigned int fb_blocks = (unsigned int)sms;   // co-resident (1024 thr => <=2/SM)
    k_rank<<<fb_blocks, 1024>>>((const float4*)hoi, ps, os,
                                (const float4*)pb, (const float4*)ob, ocls,
                                (float*)d_out, nvec, N, K, magic, T, fb_blocks);
}

// round 8
// speedup vs baseline: 6.7135x; 1.0885x over previous
#include <cuda_runtime.h>
#include <stdint.h>

#define THRESH   0.05f
#define SPEC     0.95f      // speculative cutoff; valid because hoi,ps,os < 1
#define NBINS    4096
#define CAP      65536
#define RANKMAX  4096

__device__ unsigned int g_bar;      // monotonic barrier counter (fallback only)
__device__ unsigned int g_done;     // monotonic last-out counter (k_rank)
__device__ unsigned int g_count;    // fast-path candidates (reset by last block out)
__device__ unsigned int g_count2;   // fallback candidates  (reset by last block out)
__device__ unsigned int g_hist[NBINS];
__device__ unsigned long long g_ck[CAP];    // packed keys, fast path
__device__ unsigned long long g_ck2[CAP];   // packed keys, fallback

// key packs (value, index) so that key_j > key_i  <=>  j ranks ahead of i
// (value desc, index asc — matches jax.lax.top_k). Values positive floats:
// uint compare == float compare. Keys unique (indices unique).
__device__ __forceinline__ unsigned long long mk_key(unsigned int vbits, unsigned int idx) {
    return ((unsigned long long)vbits << 32) | (unsigned long long)(0xFFFFFFFFu - idx);
}

// ---------------------------------------------------------------------------
// Kernel A: stream hoi once. Stage-1 filter h > SPEC (free: v = h*ps*os <= h).
// Stage-2 (~5% of elements): exact v > SPEC test with the two scalar loads.
// ---------------------------------------------------------------------------
__device__ __forceinline__ void scan4(float4 h, unsigned int e, unsigned long long magic,
                                      const float* __restrict__ ps,
                                      const float* __restrict__ os) {
    float m = fmaxf(fmaxf(h.x, h.y), fmaxf(h.z, h.w));
    if (m > SPEC) {
        float hv[4] = {h.x, h.y, h.z, h.w};
        #pragma unroll
        for (int j = 0; j < 4; j++) {
            if (hv[j] > SPEC) {
                unsigned int idx = e + (unsigned)j;
                unsigned int r = (unsigned int)(((unsigned long long)idx * magic) >> 33);
                float v = hv[j] * ps[r] * os[r];
                if (v > SPEC) {
                    unsigned int pos = atomicAdd(&g_count, 1u);
                    if (pos < CAP)
                        g_ck[pos] = mk_key(__float_as_uint(v), idx);
                }
            }
        }
    }
}

__global__ void __launch_bounds__(256)
k_scan(const float4* __restrict__ hoi4,
       const float*  __restrict__ ps,
       const float*  __restrict__ os,
       unsigned int nvec, unsigned int N, unsigned long long magic) {
    unsigned int stride = gridDim.x * blockDim.x;
    unsigned int q = blockIdx.x * blockDim.x + threadIdx.x;
    for (; q + 3u * stride < nvec; q += 4u * stride) {
        float4 h0 = __ldcs(hoi4 + q);
        float4 h1 = __ldcs(hoi4 + q + stride);
        float4 h2 = __ldcs(hoi4 + q + 2u * stride);
        float4 h3 = __ldcs(hoi4 + q + 3u * stride);
        scan4(h0, q * 4u, magic, ps, os);
        scan4(h1, (q + stride) * 4u, magic, ps, os);
        scan4(h2, (q + 2u * stride) * 4u, magic, ps, os);
        scan4(h3, (q + 3u * stride) * 4u, magic, ps, os);
    }
    for (; q < nvec; q += stride) {
        float4 h = __ldcs(hoi4 + q);
        scan4(h, q * 4u, magic, ps, os);
    }
    if (blockIdx.x == 0 && threadIdx.x == 0) {
        for (unsigned int e = nvec * 4u; e < N; e++) {
            float h = ((const float*)hoi4)[e];
            if (h > SPEC) {
                unsigned int r = (unsigned int)(((unsigned long long)e * magic) >> 33);
                float v = h * ps[r] * os[r];
                if (v > SPEC) {
                    unsigned int pos = atomicAdd(&g_count, 1u);
                    if (pos < CAP) g_ck[pos] = mk_key(__float_as_uint(v), e);
                }
            }
        }
    }
}

// ---------------------------------------------------------------------------
// Write one ranked detection into the flat output:
//   [0,T) scores | [T,5T) pboxes | [5T,9T) oboxes | [9T,10T) ocls
//   [10T,11T) action | [11T,12T) valid
// ---------------------------------------------------------------------------
__device__ __forceinline__ void write_det(unsigned int rank, unsigned long long kb,
                                          const float4* __restrict__ pb,
                                          const float4* __restrict__ ob,
                                          const int* __restrict__ ocls,
                                          float* __restrict__ out,
                                          unsigned int K, int T,
                                          unsigned long long magic) {
    unsigned int vb = (unsigned int)(kb >> 32);
    unsigned int ix = 0xFFFFFFFFu - (unsigned int)(kb & 0xFFFFFFFFu);
    unsigned int pair = (unsigned int)(((unsigned long long)ix * magic) >> 33);
    unsigned int act  = ix - pair * K;
    out[rank] = __uint_as_float(vb);
    float4 p = pb[pair];
    float4 o = ob[pair];
    out[T + 4 * rank + 0] = p.x;  out[T + 4 * rank + 1] = p.y;
    out[T + 4 * rank + 2] = p.z;  out[T + 4 * rank + 3] = p.w;
    out[5 * T + 4 * rank + 0] = o.x;  out[5 * T + 4 * rank + 1] = o.y;
    out[5 * T + 4 * rank + 2] = o.z;  out[5 * T + 4 * rank + 3] = o.w;
    out[9 * T + rank]  = (float)ocls[pair];
    out[10 * T + rank] = (float)act;
    out[11 * T + rank] = 1.0f;
}

// Warp-parallel exact rank+write over packed keys in global memory.
// Each warp takes items i = gw, gw+nwarps, ...; lanes partition j-space.
// Inner loop unrolled x4 -> 4 independent LDG.64 per step (L2-broadcast hits).
__device__ __forceinline__ void warp_rank_write(const unsigned long long* __restrict__ keys,
                                                unsigned int n,
                                                const float4* __restrict__ pb,
                                                const float4* __restrict__ ob,
                                                const int* __restrict__ ocls,
                                                float* __restrict__ out,
                                                unsigned int K, int T,
                                                unsigned long long magic) {
    unsigned int nwarps = (gridDim.x * blockDim.x) >> 5;
    unsigned int gw = (blockIdx.x * blockDim.x + threadIdx.x) >> 5;
    unsigned int lane = threadIdx.x & 31u;
    for (unsigned int i = gw; i < n; i += nwarps) {
        unsigned long long kb = keys[i];
        unsigned int cnt = 0;
        unsigned int jb = 0;
        for (; jb + 128u <= n; jb += 128u) {
            unsigned int a = 0;
            #pragma unroll
            for (int t = 0; t < 4; t++)
                a += (keys[jb + (unsigned)t * 32u + lane] > kb);
            cnt += a;
        }
        for (; jb < n; jb += 32u) {
            unsigned int j = jb + lane;
            if (j < n) cnt += (keys[j] > kb);
        }
        cnt = __reduce_add_sync(0xFFFFFFFFu, cnt);
        if (lane == 0 && cnt < (unsigned int)T)
            write_det(cnt, kb, pb, ob, ocls, out, K, T, magic);
    }
}

// Grid barrier for the (never-taken) fallback path only.
__device__ __forceinline__ void grid_barrier(unsigned int nblocks) {
    __syncthreads();
    __threadfence();
    if (threadIdx.x == 0) {
        unsigned int old = atomicAdd(&g_bar, 1u);
        unsigned int target = (old / nblocks + 1u) * nblocks;
        while (atomicAdd(&g_bar, 0u) < target) __nanosleep(256);
    }
    __syncthreads();
}

// ---------------------------------------------------------------------------
// Kernel B: fast path = warp-per-item parallel rank straight from global keys
// (no smem, no copies). Fallback = exact hist -> cutoff -> collect -> rank.
// Counter reset: last-block-out on monotonic g_done.
// ---------------------------------------------------------------------------
__global__ void __launch_bounds__(256)
k_rank(const float4* __restrict__ hoi4,
       const float*  __restrict__ ps, const float* __restrict__ os,
       const float4* __restrict__ pb, const float4* __restrict__ ob,
       const int*    __restrict__ ocls, float* __restrict__ out,
       unsigned int nvec, unsigned int N, unsigned int K,
       unsigned long long magic, int T, unsigned int nblocks) {
    unsigned int n = *(volatile unsigned int*)&g_count;   // uniform across blocks
    bool fast = (n >= (unsigned int)T && n <= RANKMAX);

    if (fast) {
        warp_rank_write(g_ck, n, pb, ob, ocls, out, K, T, magic);
    } else {
        // ===== exact fallback (all blocks take this branch uniformly) =====
        __shared__ unsigned int sh[NBINS];
        {   // zero global hist
            unsigned int stride = gridDim.x * blockDim.x;
            for (unsigned int i = blockIdx.x * blockDim.x + threadIdx.x; i < NBINS; i += stride)
                g_hist[i] = 0;
        }
        grid_barrier(nblocks);

        {   // shared-privatized histogram of v > THRESH
            for (int i = threadIdx.x; i < NBINS; i += blockDim.x) sh[i] = 0;
            __syncthreads();
            unsigned int stride = gridDim.x * blockDim.x;
            for (unsigned int q = blockIdx.x * blockDim.x + threadIdx.x; q < nvec; q += stride) {
                float4 h = hoi4[q];
                unsigned int e = q * 4u;
                float hv[4] = {h.x, h.y, h.z, h.w};
                #pragma unroll
                for (int j = 0; j < 4; j++) {
                    unsigned int idx = e + (unsigned)j;
                    unsigned int r = (unsigned int)(((unsigned long long)idx * magic) >> 33);
                    float v = hv[j] * ps[r] * os[r];
                    if (v > THRESH) {
                        unsigned int b = (unsigned int)(v * (float)NBINS);
                        if (b > NBINS - 1) b = NBINS - 1;
                        atomicAdd(&sh[b], 1u);
                    }
                }
            }
            if (blockIdx.x == 0 && threadIdx.x == 0) {
                for (unsigned int e = nvec * 4u; e < N; e++) {
                    unsigned int r = (unsigned int)(((unsigned long long)e * magic) >> 33);
                    float v = ((const float*)hoi4)[e] * ps[r] * os[r];
                    if (v > THRESH) {
                        unsigned int b = (unsigned int)(v * (float)NBINS);
                        if (b > NBINS - 1) b = NBINS - 1;
                        atomicAdd(&sh[b], 1u);
                    }
                }
            }
            __syncthreads();
            for (int i = threadIdx.x; i < NBINS; i += blockDim.x)
                if (sh[i]) atomicAdd(&g_hist[i], sh[i]);
        }
        grid_barrier(nblocks);

        __shared__ unsigned int s_cut;
        if (threadIdx.x == 0) {
            unsigned int cum = 0, cut = 0;
            for (int b = NBINS - 1; b >= 0; b--) {
                cum += g_hist[b];
                if (cum >= (unsigned int)T) { cut = (unsigned int)b; break; }
            }
            s_cut = cut;
        }
        __syncthreads();
        unsigned int cut = s_cut;

        {   // collect candidates with bin >= cutoff (packed keys)
            unsigned int stride = gridDim.x * blockDim.x;
            for (unsigned int q = blockIdx.x * blockDim.x + threadIdx.x; q < nvec; q += stride) {
                float4 h = hoi4[q];
                unsigned int e = q * 4u;
                float hv[4] = {h.x, h.y, h.z, h.w};
                #pragma unroll
                for (int j = 0; j < 4; j++) {
                    unsigned int idx = e + (unsigned)j;
                    unsigned int r = (unsigned int)(((unsigned long long)idx * magic) >> 33);
                    float v = hv[j] * ps[r] * os[r];
                    if (v > THRESH) {
                        unsigned int b = (unsigned int)(v * (float)NBINS);
                        if (b > NBINS - 1) b = NBINS - 1;
                        if (b >= cut) {
                            unsigned int pos = atomicAdd(&g_count2, 1u);
                            if (pos < CAP)
                                g_ck2[pos] = mk_key(__float_as_uint(v), idx);
                        }
                    }
                }
            }
            if (blockIdx.x == 0 && threadIdx.x == 0) {
                for (unsigned int e = nvec * 4u; e < N; e++) {
                    unsigned int r = (unsigned int)(((unsigned long long)e * magic) >> 33);
                    float v = ((const float*)hoi4)[e] * ps[r] * os[r];
                    if (v > THRESH) {
                        unsigned int b = (unsigned int)(v * (float)NBINS);
                        if (b > NBINS - 1) b = NBINS - 1;
                        if (b >= cut) {
                            unsigned int pos = atomicAdd(&g_count2, 1u);
                            if (pos < CAP)
                                g_ck2[pos] = mk_key(__float_as_uint(v), e);
                        }
                    }
                }
            }
        }
        grid_barrier(nblocks);

        unsigned int n2 = *(volatile unsigned int*)&g_count2;
        if (n2 > CAP) n2 = CAP;
        warp_rank_write(g_ck2, n2, pb, ob, ocls, out, K, T, magic);

        // zero-pad unfilled slots (n2 < T): block 0
        if (blockIdx.x == 0) {
            for (int s = threadIdx.x; s < T; s += blockDim.x) {
                if ((unsigned int)s >= n2) {
                    out[s] = 0.0f;
                    #pragma unroll
                    for (int d = 0; d < 4; d++) {
                        out[T + 4 * s + d] = 0.0f;
                        out[5 * T + 4 * s + d] = 0.0f;
                    }
                    out[9 * T + s] = 0.0f;
                    out[10 * T + s] = 0.0f;
                    out[11 * T + s] = 0.0f;
                }
            }
        }
    }

    // ---- last-block-out counter reset (race-free: every block's read of
    // g_count precedes its arrival; reset fires only at the final arrival) ----
    __syncthreads();
    __threadfence();
    if (threadIdx.x == 0) {
        unsigned int old = atomicAdd(&g_done, 1u);
        if ((old % nblocks) == nblocks - 1u) {
            g_count = 0;
            g_count2 = 0;
        }
    }
}

// ---------------------------------------------------------------------------
extern "C" void kernel_launch(void* const* d_in, const int* in_sizes, int n_in,
                              void* d_out, int out_size) {
    const float* pb   = (const float*)d_in[0];
    const float* ob   = (const float*)d_in[1];
    const float* ps   = (const float*)d_in[2];
    const float* os   = (const float*)d_in[3];
    const int*   ocls = (const int*)d_in[4];
    const float* hoi  = (const float*)d_in[5];

    int R = in_sizes[2];
    unsigned int N = (unsigned int)in_sizes[5];
    unsigned int K = N / (unsigned int)R;
    int T = out_size / 12;
    unsigned int nvec = N / 4u;
    unsigned long long magic = ((1ULL << 33) + K - 1) / K;  // exact e/K, e < 2^33/K

    int dev = 0, sms = 148;
    cudaGetDevice(&dev);
    cudaDeviceGetAttribute(&sms, cudaDevAttrMultiProcessorCount, dev);

    unsigned int scan_blocks = (unsigned int)(sms * 8);
    k_scan<<<scan_blocks, 256>>>((const float4*)hoi, ps, os, nvec, N, magic);

    unsigned int fb_blocks = (unsigned int)sms;   // co-resident for fallback barrier
    k_rank<<<fb_blocks, 256>>>((const float4*)hoi, ps, os,
                               (const float4*)pb, (const float4*)ob, ocls,
                               (float*)d_out, nvec, N, K, magic, T, fb_blocks);
}